// round 11
// baseline (speedup 1.0000x reference)
#include <cuda_runtime.h>
#include <cuda_fp16.h>
#include <cstdint>
#include <cstddef>

#define DEV __device__ __forceinline__

// ---------------- problem constants ----------------
static constexpr int BB = 32;
static constexpr int SEQ = 2048;
static constexpr int DD = 1024;    // K
static constexpr int SZ = 1024;    // SIZE

static constexpr int M_TILE = 128;
static constexpr int N_TILE = 128;            // 2 CTAs/SM
static constexpr int PASSES = SZ / N_TILE;    // 8
static constexpr int K_CHUNK = 64;            // K elems per chunk
static constexpr int NCHUNK = DD / K_CHUNK;   // 16
static constexpr int TOTAL_CHUNKS = PASSES * NCHUNK;   // 128
static constexpr int THREADS = 128;           // 4 warps: 2m x 2n, warp tile 64x64
static constexpr int KPADF = 68;              // A row: 64 fp32 + pad (272 B)
static constexpr int KPH = 72;                // B row: 64 halves + pad (144 B)

// smem: 2-stage ring of (A fp32 | B fp16) + partial buffer
static constexpr int A_BYTES = M_TILE * KPADF * 4;        // 34816
static constexpr int B_BYTES = N_TILE * KPH * 2;          // 18432
static constexpr int STAGE_BYTES = A_BYTES + B_BYTES;     // 53248
static constexpr int NSTAGE = 2;
static constexpr int RING_BYTES = NSTAGE * STAGE_BYTES;   // 106496
static constexpr int SMEM_BYTES = RING_BYTES + M_TILE * 4;  // 107008 -> 2 CTAs/SM

// scratch: fp16 WO + packed (v, term2) table  (X consumed directly as fp32)
__device__ __half g_WOh[(size_t)SZ * DD];        // 2 MB
__device__ float2 g_vt2[BB * SZ];                // {v[n], term2[b][n]}

// ---------------- helpers ----------------
DEV uint32_t smem_u32(const void* p) {
    uint32_t a;
    asm("{ .reg .u64 t; cvta.to.shared.u64 t, %1; cvt.u32.u64 %0, t; }" : "=r"(a) : "l"(p));
    return a;
}
DEV void cp16(uint32_t s, const void* g) {
    asm volatile("cp.async.cg.shared.global [%0], [%1], 16;" :: "r"(s), "l"(g));
}
DEV void cp_commit() { asm volatile("cp.async.commit_group;" ::: "memory"); }
template <int N> DEV void cp_wait() { asm volatile("cp.async.wait_group %0;" :: "n"(N) : "memory"); }

DEV float tanh_fast(float x) {
    float y;
    asm("tanh.approx.f32 %0, %1;" : "=f"(y) : "f"(x));
    return y;
}
DEV uint32_t pack_h2(float lo, float hi) {
    __half2 h = __floats2half2_rn(lo, hi);
    return *(uint32_t*)&h;
}

DEV void mma_f16(float* d, const uint32_t* a, const uint32_t* b) {
    asm volatile(
        "mma.sync.aligned.m16n8k16.row.col.f32.f16.f16.f32 "
        "{%0,%1,%2,%3}, {%4,%5,%6,%7}, {%8,%9}, {%0,%1,%2,%3};"
        : "+f"(d[0]), "+f"(d[1]), "+f"(d[2]), "+f"(d[3])
        : "r"(a[0]), "r"(a[1]), "r"(a[2]), "r"(a[3]), "r"(b[0]), "r"(b[1]));
}

// Stage chunk T into ring slot `slot`.
// A: [128 x 64 fp32] from X = 2048 cp16 (16/thread); B: [128 x 64 h] from WOh = 1024 cp16.
DEV void stage_T(char* smem, int slot, int T, const float* Xbase, int tid) {
    const int kc = T & (NCHUNK - 1);
    const int p = T >> 4;
    const float* asrc = Xbase + kc * K_CHUNK;
    const __half* bsrc = g_WOh + (size_t)p * N_TILE * DD + kc * K_CHUNK;
    const uint32_t sa = smem_u32(smem) + (uint32_t)slot * STAGE_BYTES;
    const uint32_t sbB = sa + A_BYTES;
#pragma unroll
    for (int it = 0; it < 16; it++) {   // A fp32: 16 cp16 per row
        const int gidx = tid + it * THREADS;
        const int r = gidx >> 4, c = gidx & 15;
        cp16(sa + (uint32_t)(r * KPADF * 4 + c * 16), asrc + (size_t)r * DD + c * 4);
    }
#pragma unroll
    for (int it = 0; it < 8; it++) {    // B fp16: 8 cp16 per row
        const int gidx = tid + it * THREADS;
        const int r = gidx >> 3, c = gidx & 7;
        cp16(sbB + (uint32_t)(r * KPH * 2 + c * 16), bsrc + (size_t)r * DD + c * 8);
    }
}

// ---------------- prepass: WO fp32 -> fp16 (rn) ----------------
__global__ void tohalf_kernel(const float* __restrict__ src, uint2* __restrict__ dst, int n4) {
    int i = blockIdx.x * blockDim.x + threadIdx.x;
    if (i >= n4) return;
    float4 u = ((const float4*)src)[i];
    __half2 h0 = __floats2half2_rn(u.x, u.y);
    __half2 h1 = __floats2half2_rn(u.z, u.w);
    uint2 o;
    o.x = *(uint32_t*)&h0;
    o.y = *(uint32_t*)&h1;
    dst[i] = o;
}

// ---------------- term2 = WG @ g, packed with v ----------------
__global__ void term2_kernel(const float* __restrict__ WG, const float* __restrict__ g,
                             const float* __restrict__ v) {
    __shared__ float4 gs[256];
    const int b = blockIdx.y;
    gs[threadIdx.x] = ((const float4*)(g + (size_t)b * DD))[threadIdx.x];
    __syncthreads();
    const int w = threadIdx.x >> 5, l = threadIdx.x & 31;
    const int n = blockIdx.x * 8 + w;
    const float4* wg4 = (const float4*)(WG + (size_t)n * DD);
    float s = 0.f;
#pragma unroll
    for (int i = 0; i < 8; i++) {
        float4 a = wg4[l + 32 * i];
        float4 gg = gs[l + 32 * i];
        s += a.x * gg.x + a.y * gg.y + a.z * gg.z + a.w * gg.w;
    }
#pragma unroll
    for (int o = 16; o; o >>= 1) s += __shfl_xor_sync(0xFFFFFFFFu, s, o);
    if (l == 0) g_vt2[b * SZ + n] = make_float2(v[n], s);
}

// ---------------- fused GEMM(fp16 mma.sync) + tanh + v-dot ----------------
__global__ __launch_bounds__(THREADS, 2)
void fused_kernel(const float* __restrict__ X, float* __restrict__ out) {
    extern __shared__ char smem[];
    const int tid = threadIdx.x;
    const int lane = tid & 31, wid = tid >> 5;
    const int wm = wid >> 1, wn = wid & 1;      // 2 x 2 warp grid; warp tile 64x64
    const int m0 = blockIdx.x * M_TILE;
    const int bidx = m0 >> 11;                  // batch index

    float* part = (float*)(smem + RING_BYTES);
    for (int i = tid; i < M_TILE; i += THREADS) part[i] = 0.f;

    const float* Xbase = X + (size_t)m0 * DD;
    const float4* vt4 = (const float4*)(g_vt2 + (size_t)bidx * SZ);

    float racc[8];
#pragma unroll
    for (int j = 0; j < 8; j++) racc[j] = 0.f;

    float acc[4][8][4];
#pragma unroll
    for (int mt = 0; mt < 4; mt++)
#pragma unroll
        for (int nt = 0; nt < 8; nt++)
#pragma unroll
            for (int q = 0; q < 4; q++) acc[mt][nt][q] = 0.f;

    const int ar = lane >> 2;   // fragment row
    const int ak = lane & 3;    // fragment k-pair

    // prologue: stage chunk 0 into slot 0
    stage_T(smem, 0, 0, Xbase, tid);
    cp_commit();

#pragma unroll 1
    for (int T = 0; T < TOTAL_CHUNKS; T++) {
        cp_wait<0>();        // my copies of chunk T complete
        __syncthreads();     // everyone's chunk T visible; slot (T+1)&1 reads (from T-1) drained

        if (T + 1 < TOTAL_CHUNKS) stage_T(smem, (T + 1) & 1, T + 1, Xbase, tid);
        cp_commit();         // proceeds concurrently with compute below

        const char* stage = smem + (size_t)(T & 1) * STAGE_BYTES;
        const float* Af = (const float*)stage;                    // fp32 A
        const uint32_t* Bs = (const uint32_t*)(stage + A_BYTES);  // fp16 B

#pragma unroll
        for (int k16 = 0; k16 < 4; k16++) {     // four m16n8k16 steps cover 64 k
            const int ko = k16 * 8;             // k-pair offset within row
            uint32_t a[4][4], b[8][2];
#pragma unroll
            for (int mt = 0; mt < 4; mt++) {
                const int r0 = (wm * 64 + mt * 16 + ar) * KPADF + 2 * (ko + ak);
                const float2 f0 = *(const float2*)(Af + r0);                   // row, k 2(ko+ak)
                const float2 f1 = *(const float2*)(Af + r0 + 8 * KPADF);       // row+8
                const float2 f2 = *(const float2*)(Af + r0 + 8);               // k +8
                const float2 f3 = *(const float2*)(Af + r0 + 8 * KPADF + 8);
                a[mt][0] = pack_h2(f0.x, f0.y);
                a[mt][1] = pack_h2(f1.x, f1.y);
                a[mt][2] = pack_h2(f2.x, f2.y);
                a[mt][3] = pack_h2(f3.x, f3.y);
            }
#pragma unroll
            for (int nt = 0; nt < 8; nt++) {
                const int nb = (wn * 64 + nt * 8 + ar) * (KPH / 2) + ko + ak;
                b[nt][0] = Bs[nb];
                b[nt][1] = Bs[nb + 4];
            }
#pragma unroll
            for (int mt = 0; mt < 4; mt++)
#pragma unroll
                for (int nt = 0; nt < 8; nt++)
                    mma_f16(acc[mt][nt], a[mt], b[nt]);
        }

        // ---- pass boundary: epilogue (registers + L2 table; no barrier) ----
        if ((T & (NCHUNK - 1)) == NCHUNK - 1) {
            const int p = T >> 4;
#pragma unroll
            for (int mt = 0; mt < 4; mt++) {
#pragma unroll
                for (int nt = 0; nt < 8; nt++) {
                    const int gn = p * N_TILE + wn * 64 + nt * 8 + 2 * ak;
                    const float4 w = __ldg(&vt4[gn >> 1]);   // {v0, t20, v1, t21}
                    racc[mt * 2] += w.x * tanh_fast(acc[mt][nt][0] + w.y)
                                  + w.z * tanh_fast(acc[mt][nt][1] + w.w);
                    racc[mt * 2 + 1] += w.x * tanh_fast(acc[mt][nt][2] + w.y)
                                      + w.z * tanh_fast(acc[mt][nt][3] + w.w);
                    acc[mt][nt][0] = 0.f; acc[mt][nt][1] = 0.f;
                    acc[mt][nt][2] = 0.f; acc[mt][nt][3] = 0.f;
                }
            }
        }
    }

    // reduce over the 4 lanes of each column group
#pragma unroll
    for (int j = 0; j < 8; j++) {
        racc[j] += __shfl_xor_sync(0xFFFFFFFFu, racc[j], 1);
        racc[j] += __shfl_xor_sync(0xFFFFFFFFu, racc[j], 2);
    }
    if (ak == 0) {
#pragma unroll
        for (int j = 0; j < 8; j++) {
            const int row = wm * 64 + (j >> 1) * 16 + ar + (j & 1) * 8;
            atomicAdd(&part[row], racc[j]);
        }
    }
    __syncthreads();
    if (tid < M_TILE) out[m0 + tid] = part[tid];
}

// ---------------- launch ----------------
extern "C" void kernel_launch(void* const* d_in, const int* in_sizes, int n_in,
                              void* d_out, int out_size) {
    const float* X  = (const float*)d_in[0];   // inputs [B,S,D]
    const float* g  = (const float*)d_in[1];   // g [B,D]
    const float* WO = (const float*)d_in[2];   // WO [SIZE,D]
    const float* WG = (const float*)d_in[3];   // WG [SIZE,D]
    const float* v  = (const float*)d_in[4];   // v [1,SIZE]
    float* out = (float*)d_out;

    __half* WOh; cudaGetSymbolAddress((void**)&WOh, g_WOh);

    cudaFuncSetAttribute(fused_kernel, cudaFuncAttributeMaxDynamicSharedMemorySize, SMEM_BYTES);

    const int nW4 = SZ * DD / 4;
    tohalf_kernel<<<nW4 / 256, 256>>>(WO, (uint2*)WOh, nW4);
    term2_kernel<<<dim3(SZ / 8, BB), 256>>>(WG, g, v);

    fused_kernel<<<(BB * SEQ) / M_TILE, THREADS, SMEM_BYTES>>>(X, out);
}

// round 12
// speedup vs baseline: 1.1059x; 1.1059x over previous
#include <cuda_runtime.h>
#include <cuda_fp16.h>
#include <cstdint>
#include <cstddef>

#define DEV __device__ __forceinline__

// ---------------- problem constants ----------------
static constexpr int BB = 32;
static constexpr int SEQ = 2048;
static constexpr int DD = 1024;    // K
static constexpr int SZ = 1024;    // SIZE

static constexpr int M_TILE = 128;
static constexpr int N_TILE = 128;            // 2 CTAs/SM
static constexpr int PASSES = SZ / N_TILE;    // 8
static constexpr int K_CHUNK = 64;            // halves of K per chunk
static constexpr int NCHUNK = DD / K_CHUNK;   // 16
static constexpr int TOTAL_CHUNKS = PASSES * NCHUNK;   // 128
static constexpr int THREADS = 128;           // 4 warps: 2m x 2n, warp tile 64x64
static constexpr int KPH = 72;                // halves per smem row (144 B; conflict-free)
static constexpr int NTILES = (BB * SEQ) / M_TILE;     // 512
static constexpr int GRID = 304;              // persistent: 2 CTAs x 152 SMs

// smem: 3-stage ring of (A|B) halves + tile-id word + partial buffer
static constexpr int A_HALVES = M_TILE * KPH;             // 9216
static constexpr int B_HALVES = N_TILE * KPH;             // 9216
static constexpr int STAGE_HALVES = A_HALVES + B_HALVES;  // 18432
static constexpr int NSTAGE = 3;
static constexpr int RING_BYTES = NSTAGE * STAGE_HALVES * 2;   // 110592
static constexpr int SMEM_BYTES = RING_BYTES + M_TILE * 4 + 16;  // ~111 KB -> 2 CTAs/SM

// scratch: fp16 copies + packed (v, term2) table + tile counter
__device__ __half g_Xh[(size_t)BB * SEQ * DD];   // 128 MB
__device__ __half g_WOh[(size_t)SZ * DD];        // 2 MB
__device__ float2 g_vt2[BB * SZ];                // {v[n], term2[b][n]}
__device__ unsigned int g_tile_ctr;

// ---------------- helpers ----------------
DEV uint32_t smem_u32(const void* p) {
    uint32_t a;
    asm("{ .reg .u64 t; cvta.to.shared.u64 t, %1; cvt.u32.u64 %0, t; }" : "=r"(a) : "l"(p));
    return a;
}
DEV void cp16(uint32_t s, const void* g) {
    asm volatile("cp.async.cg.shared.global [%0], [%1], 16;" :: "r"(s), "l"(g));
}
DEV void cp_commit() { asm volatile("cp.async.commit_group;" ::: "memory"); }
template <int N> DEV void cp_wait() { asm volatile("cp.async.wait_group %0;" :: "n"(N) : "memory"); }

DEV float tanh_fast(float x) {
    float y;
    asm("tanh.approx.f32 %0, %1;" : "=f"(y) : "f"(x));
    return y;
}

DEV void mma_f16(float* d, const uint32_t* a, const uint32_t* b) {
    asm volatile(
        "mma.sync.aligned.m16n8k16.row.col.f32.f16.f16.f32 "
        "{%0,%1,%2,%3}, {%4,%5,%6,%7}, {%8,%9}, {%0,%1,%2,%3};"
        : "+f"(d[0]), "+f"(d[1]), "+f"(d[2]), "+f"(d[3])
        : "r"(a[0]), "r"(a[1]), "r"(a[2]), "r"(a[3]), "r"(b[0]), "r"(b[1]));
}

// Stage chunk T (pass = T/16, kc = T%16) of tile `Xbase` into ring slot `slot`.
DEV void stage_T(char* smem, int slot, int T, const __half* Xbase, int tid) {
    const int kc = T & (NCHUNK - 1);
    const int p = T >> 4;
    const __half* asrc = Xbase + kc * K_CHUNK;
    const __half* bsrc = g_WOh + (size_t)p * N_TILE * DD + kc * K_CHUNK;
    const uint32_t sa = smem_u32(smem) + (uint32_t)slot * STAGE_HALVES * 2u;
    const uint32_t sbB = sa + A_HALVES * 2u;
#pragma unroll
    for (int it = 0; it < 8; it++) {   // A: [128 x 64h] = 1024 cp16
        const int gidx = tid + it * THREADS;
        const int r = gidx >> 3, c = gidx & 7;
        cp16(sa + (uint32_t)(r * KPH * 2 + c * 16), asrc + (size_t)r * DD + c * 8);
    }
#pragma unroll
    for (int it = 0; it < 8; it++) {   // B: [128 x 64h] = 1024 cp16
        const int gidx = tid + it * THREADS;
        const int r = gidx >> 3, c = gidx & 7;
        cp16(sbB + (uint32_t)(r * KPH * 2 + c * 16), bsrc + (size_t)r * DD + c * 8);
    }
}

// ---------------- prepass: fp32 -> fp16 (rn) ----------------
__global__ void tohalf_kernel(const float* __restrict__ src, uint2* __restrict__ dst, int n4) {
    int i = blockIdx.x * blockDim.x + threadIdx.x;
    if (i >= n4) return;
    float4 u = ((const float4*)src)[i];
    __half2 h0 = __floats2half2_rn(u.x, u.y);
    __half2 h1 = __floats2half2_rn(u.z, u.w);
    uint2 o;
    o.x = *(uint32_t*)&h0;
    o.y = *(uint32_t*)&h1;
    dst[i] = o;
}

// ---------------- term2 = WG @ g, packed with v; also resets tile counter ----------------
__global__ void term2_kernel(const float* __restrict__ WG, const float* __restrict__ g,
                             const float* __restrict__ v) {
    if (blockIdx.x == 0 && blockIdx.y == 0 && threadIdx.x == 0) g_tile_ctr = 0u;
    __shared__ float4 gs[256];
    const int b = blockIdx.y;
    gs[threadIdx.x] = ((const float4*)(g + (size_t)b * DD))[threadIdx.x];
    __syncthreads();
    const int w = threadIdx.x >> 5, l = threadIdx.x & 31;
    const int n = blockIdx.x * 8 + w;
    const float4* wg4 = (const float4*)(WG + (size_t)n * DD);
    float s = 0.f;
#pragma unroll
    for (int i = 0; i < 8; i++) {
        float4 a = wg4[l + 32 * i];
        float4 gg = gs[l + 32 * i];
        s += a.x * gg.x + a.y * gg.y + a.z * gg.z + a.w * gg.w;
    }
#pragma unroll
    for (int o = 16; o; o >>= 1) s += __shfl_xor_sync(0xFFFFFFFFu, s, o);
    if (l == 0) g_vt2[b * SZ + n] = make_float2(v[n], s);
}

// ---------------- persistent fused GEMM(fp16 mma.sync) + tanh + v-dot ----------------
__global__ __launch_bounds__(THREADS, 2)
void fused_kernel(float* __restrict__ out) {
    extern __shared__ char smem[];
    const int tid = threadIdx.x;
    const int lane = tid & 31, wid = tid >> 5;
    const int wm = wid >> 1, wn = wid & 1;      // 2 x 2 warp grid; warp tile 64x64
    const int ar = lane >> 2;   // fragment row
    const int ak = lane & 3;    // fragment k-pair

    float* part = (float*)(smem + RING_BYTES);
    int* tile_sh = (int*)(smem + RING_BYTES + M_TILE * 4);

    for (;;) {
        // ---- grab next tile ----
        if (tid == 0) *tile_sh = (int)atomicAdd(&g_tile_ctr, 1u);
        __syncthreads();   // publish tile id; also: prior tile's part reads done
        const int tile = *tile_sh;
        if (tile >= NTILES) break;

        const int m0 = tile * M_TILE;
        const int bidx = m0 >> 11;
        const __half* Xbase = g_Xh + (size_t)m0 * DD;
        const float4* vt4 = (const float4*)(g_vt2 + (size_t)bidx * SZ);

        for (int i = tid; i < M_TILE; i += THREADS) part[i] = 0.f;

        float racc[8];
#pragma unroll
        for (int j = 0; j < 8; j++) racc[j] = 0.f;

        float acc[4][8][4];
#pragma unroll
        for (int mt = 0; mt < 4; mt++)
#pragma unroll
            for (int nt = 0; nt < 8; nt++)
#pragma unroll
                for (int q = 0; q < 4; q++) acc[mt][nt][q] = 0.f;

        // prologue: prefetch chunks 0 and 1
        stage_T(smem, 0, 0, Xbase, tid);
        cp_commit();
        stage_T(smem, 1, 1, Xbase, tid);
        cp_commit();

        int bufR = 0;   // slot holding chunk T
        int bufS = 2;   // slot to stage chunk T+2 into

#pragma unroll 1
        for (int T = 0; T < TOTAL_CHUNKS; T++) {
            cp_wait<1>();        // own copies of chunk T complete
            __syncthreads();     // chunk T visible to all; slot bufS reads drained

            if (T + 2 < TOTAL_CHUNKS) stage_T(smem, bufS, T + 2, Xbase, tid);
            cp_commit();         // keep group counts aligned

            const uint32_t* As = (const uint32_t*)(smem + (size_t)bufR * STAGE_HALVES * 2);
            const uint32_t* Bs = As + A_HALVES / 2;

#pragma unroll
            for (int k16 = 0; k16 < 4; k16++) {
                const int ko = k16 * 8;
                uint32_t a[4][4], b[8][2];
#pragma unroll
                for (int mt = 0; mt < 4; mt++) {
                    const int r0 = (wm * 64 + mt * 16 + ar) * (KPH / 2) + ko + ak;
                    a[mt][0] = As[r0];
                    a[mt][1] = As[r0 + 8 * (KPH / 2)];
                    a[mt][2] = As[r0 + 4];
                    a[mt][3] = As[r0 + 8 * (KPH / 2) + 4];
                }
#pragma unroll
                for (int nt = 0; nt < 8; nt++) {
                    const int nb = (wn * 64 + nt * 8 + ar) * (KPH / 2) + ko + ak;
                    b[nt][0] = Bs[nb];
                    b[nt][1] = Bs[nb + 4];
                }
#pragma unroll
                for (int mt = 0; mt < 4; mt++)
#pragma unroll
                    for (int nt = 0; nt < 8; nt++)
                        mma_f16(acc[mt][nt], a[mt], b[nt]);
            }

            // ---- pass boundary: epilogue (registers + L2 table; no barrier) ----
            if ((T & (NCHUNK - 1)) == NCHUNK - 1) {
                const int p = T >> 4;
#pragma unroll
                for (int mt = 0; mt < 4; mt++) {
#pragma unroll
                    for (int nt = 0; nt < 8; nt++) {
                        const int gn = p * N_TILE + wn * 64 + nt * 8 + 2 * ak;
                        const float4 w = __ldg(&vt4[gn >> 1]);   // {v0, t20, v1, t21}
                        racc[mt * 2] += w.x * tanh_fast(acc[mt][nt][0] + w.y)
                                      + w.z * tanh_fast(acc[mt][nt][1] + w.w);
                        racc[mt * 2 + 1] += w.x * tanh_fast(acc[mt][nt][2] + w.y)
                                          + w.z * tanh_fast(acc[mt][nt][3] + w.w);
                        acc[mt][nt][0] = 0.f; acc[mt][nt][1] = 0.f;
                        acc[mt][nt][2] = 0.f; acc[mt][nt][3] = 0.f;
                    }
                }
            }

            bufR = (bufR == 2) ? 0 : bufR + 1;
            bufS = (bufS == 2) ? 0 : bufS + 1;
        }

        // ---- reduce and write this tile ----
#pragma unroll
        for (int j = 0; j < 8; j++) {
            racc[j] += __shfl_xor_sync(0xFFFFFFFFu, racc[j], 1);
            racc[j] += __shfl_xor_sync(0xFFFFFFFFu, racc[j], 2);
        }
        if (ak == 0) {
#pragma unroll
            for (int j = 0; j < 8; j++) {
                const int row = wm * 64 + (j >> 1) * 16 + ar + (j & 1) * 8;
                atomicAdd(&part[row], racc[j]);
            }
        }
        __syncthreads();
        if (tid < M_TILE) out[m0 + tid] = part[tid];
        // loop-top __syncthreads orders these part reads vs next tile's zeroing
    }
}

// ---------------- launch ----------------
extern "C" void kernel_launch(void* const* d_in, const int* in_sizes, int n_in,
                              void* d_out, int out_size) {
    const float* X  = (const float*)d_in[0];   // inputs [B,S,D]
    const float* g  = (const float*)d_in[1];   // g [B,D]
    const float* WO = (const float*)d_in[2];   // WO [SIZE,D]
    const float* WG = (const float*)d_in[3];   // WG [SIZE,D]
    const float* v  = (const float*)d_in[4];   // v [1,SIZE]
    float* out = (float*)d_out;

    __half* Xh;  cudaGetSymbolAddress((void**)&Xh,  g_Xh);
    __half* WOh; cudaGetSymbolAddress((void**)&WOh, g_WOh);

    cudaFuncSetAttribute(fused_kernel, cudaFuncAttributeMaxDynamicSharedMemorySize, SMEM_BYTES);

    const int nX4 = BB * SEQ * DD / 4;
    tohalf_kernel<<<nX4 / 256, 256>>>(X, (uint2*)Xh, nX4);
    const int nW4 = SZ * DD / 4;
    tohalf_kernel<<<nW4 / 256, 256>>>(WO, (uint2*)WOh, nW4);
    term2_kernel<<<dim3(SZ / 8, BB), 256>>>(WG, g, v);   // also resets g_tile_ctr

    fused_kernel<<<GRID, THREADS, SMEM_BYTES>>>(out);
}

// round 13
// speedup vs baseline: 1.5569x; 1.4078x over previous
#include <cuda_runtime.h>
#include <cuda_fp16.h>
#include <cstdint>
#include <cstddef>

#define DEV __device__ __forceinline__

// ---------------- problem constants ----------------
static constexpr int BB = 32;
static constexpr int SEQ = 2048;
static constexpr int DD = 1024;    // K
static constexpr int SZ = 1024;    // SIZE

static constexpr int M_TILE = 128;
static constexpr int N_TILE = 128;            // 2 CTAs/SM
static constexpr int PASSES = SZ / N_TILE;    // 8
static constexpr int K_CHUNK = 64;            // halves of K per chunk
static constexpr int NCHUNK = DD / K_CHUNK;   // 16
static constexpr int TOTAL_CHUNKS = PASSES * NCHUNK;   // 128
static constexpr int THREADS = 128;           // 4 warps: 2m x 2n, warp tile 64x64
static constexpr int KPH = 72;                // halves per smem row (144 B; LDSM conflict-free)

// smem: 3-stage ring of (A|B) halves + partial buffer
static constexpr int A_HALVES = M_TILE * KPH;             // 9216
static constexpr int B_HALVES = N_TILE * KPH;             // 9216
static constexpr int STAGE_HALVES = A_HALVES + B_HALVES;  // 18432
static constexpr int NSTAGE = 3;
static constexpr int RING_BYTES = NSTAGE * STAGE_HALVES * 2;   // 110592
static constexpr int SMEM_BYTES = RING_BYTES + M_TILE * 4;     // 111104 -> 2 CTAs/SM

// scratch: fp16 copies + packed (v, term2) table
__device__ __half g_Xh[(size_t)BB * SEQ * DD];   // 128 MB
__device__ __half g_WOh[(size_t)SZ * DD];        // 2 MB
__device__ float2 g_vt2[BB * SZ];                // {v[n], term2[b][n]}

// ---------------- helpers ----------------
DEV uint32_t smem_u32(const void* p) {
    uint32_t a;
    asm("{ .reg .u64 t; cvta.to.shared.u64 t, %1; cvt.u32.u64 %0, t; }" : "=r"(a) : "l"(p));
    return a;
}
DEV void cp16(uint32_t s, const void* g) {
    asm volatile("cp.async.cg.shared.global [%0], [%1], 16;" :: "r"(s), "l"(g));
}
DEV void cp_commit() { asm volatile("cp.async.commit_group;" ::: "memory"); }
template <int N> DEV void cp_wait() { asm volatile("cp.async.wait_group %0;" :: "n"(N) : "memory"); }

DEV float tanh_fast(float x) {
    float y;
    asm("tanh.approx.f32 %0, %1;" : "=f"(y) : "f"(x));
    return y;
}

DEV void ldsm4(uint32_t& r0, uint32_t& r1, uint32_t& r2, uint32_t& r3, uint32_t addr) {
    asm volatile("ldmatrix.sync.aligned.m8n8.x4.shared.b16 {%0,%1,%2,%3}, [%4];"
                 : "=r"(r0), "=r"(r1), "=r"(r2), "=r"(r3) : "r"(addr));
}

DEV void mma_f16(float* d, const uint32_t* a, const uint32_t* b) {
    asm volatile(
        "mma.sync.aligned.m16n8k16.row.col.f32.f16.f16.f32 "
        "{%0,%1,%2,%3}, {%4,%5,%6,%7}, {%8,%9}, {%0,%1,%2,%3};"
        : "+f"(d[0]), "+f"(d[1]), "+f"(d[2]), "+f"(d[3])
        : "r"(a[0]), "r"(a[1]), "r"(a[2]), "r"(a[3]), "r"(b[0]), "r"(b[1]));
}

// Stage chunk T (pass = T/16, kc = T%16) into ring slot `slot`.
DEV void stage_T(char* smem, int slot, int T, const __half* Xbase, int tid) {
    const int kc = T & (NCHUNK - 1);
    const int p = T >> 4;
    const __half* asrc = Xbase + kc * K_CHUNK;
    const __half* bsrc = g_WOh + (size_t)p * N_TILE * DD + kc * K_CHUNK;
    const uint32_t sa = smem_u32(smem) + (uint32_t)slot * STAGE_HALVES * 2u;
    const uint32_t sbB = sa + A_HALVES * 2u;
#pragma unroll
    for (int it = 0; it < 8; it++) {   // A: [128 x 64h] = 1024 cp16
        const int gidx = tid + it * THREADS;
        const int r = gidx >> 3, c = gidx & 7;
        cp16(sa + (uint32_t)(r * KPH * 2 + c * 16), asrc + (size_t)r * DD + c * 8);
    }
#pragma unroll
    for (int it = 0; it < 8; it++) {   // B: [128 x 64h] = 1024 cp16
        const int gidx = tid + it * THREADS;
        const int r = gidx >> 3, c = gidx & 7;
        cp16(sbB + (uint32_t)(r * KPH * 2 + c * 16), bsrc + (size_t)r * DD + c * 8);
    }
}

// ---------------- prepass: fp32 -> fp16 (rn) ----------------
__global__ void tohalf_kernel(const float* __restrict__ src, uint2* __restrict__ dst, int n4) {
    int i = blockIdx.x * blockDim.x + threadIdx.x;
    if (i >= n4) return;
    float4 u = ((const float4*)src)[i];
    __half2 h0 = __floats2half2_rn(u.x, u.y);
    __half2 h1 = __floats2half2_rn(u.z, u.w);
    uint2 o;
    o.x = *(uint32_t*)&h0;
    o.y = *(uint32_t*)&h1;
    dst[i] = o;
}

// ---------------- term2 = WG @ g, packed with v ----------------
__global__ void term2_kernel(const float* __restrict__ WG, const float* __restrict__ g,
                             const float* __restrict__ v) {
    __shared__ float4 gs[256];
    const int b = blockIdx.y;
    gs[threadIdx.x] = ((const float4*)(g + (size_t)b * DD))[threadIdx.x];
    __syncthreads();
    const int w = threadIdx.x >> 5, l = threadIdx.x & 31;
    const int n = blockIdx.x * 8 + w;
    const float4* wg4 = (const float4*)(WG + (size_t)n * DD);
    float s = 0.f;
#pragma unroll
    for (int i = 0; i < 8; i++) {
        float4 a = wg4[l + 32 * i];
        float4 gg = gs[l + 32 * i];
        s += a.x * gg.x + a.y * gg.y + a.z * gg.z + a.w * gg.w;
    }
#pragma unroll
    for (int o = 16; o; o >>= 1) s += __shfl_xor_sync(0xFFFFFFFFu, s, o);
    if (l == 0) g_vt2[b * SZ + n] = make_float2(v[n], s);
}

// ---------------- fused GEMM(fp16 mma.sync + ldmatrix) + tanh + v-dot ----------------
__global__ __launch_bounds__(THREADS, 2)
void fused_kernel(float* __restrict__ out) {
    extern __shared__ char smem[];
    const int tid = threadIdx.x;
    const int lane = tid & 31, wid = tid >> 5;
    const int wm = wid >> 1, wn = wid & 1;      // 2 x 2 warp grid; warp tile 64x64
    const int m0 = blockIdx.x * M_TILE;
    const int bidx = m0 >> 11;

    float* part = (float*)(smem + RING_BYTES);
    for (int i = tid; i < M_TILE; i += THREADS) part[i] = 0.f;

    const __half* Xbase = g_Xh + (size_t)m0 * DD;
    const float4* vt4 = (const float4*)(g_vt2 + (size_t)bidx * SZ);

    float racc[8];
#pragma unroll
    for (int j = 0; j < 8; j++) racc[j] = 0.f;

    float acc[4][8][4];
#pragma unroll
    for (int mt = 0; mt < 4; mt++)
#pragma unroll
        for (int nt = 0; nt < 8; nt++)
#pragma unroll
            for (int q = 0; q < 4; q++) acc[mt][nt][q] = 0.f;

    const int ar = lane >> 2;   // fragment row (for epilogue indexing)
    const int ak = lane & 3;    // fragment k-pair (for epilogue indexing)

    // ldmatrix per-thread address offsets (constant across chunks)
    const int lrow = lane & 7;
    const int msel = lane >> 3;            // 0..3
    const int mro = (msel & 1) * 8 + lrow; // row-within-16 block
    const int kho = (msel >> 1) * 8;       // k-halves offset (0 or 8)
    uint32_t offA[4], offB[4];
#pragma unroll
    for (int mt = 0; mt < 4; mt++)
        offA[mt] = (uint32_t)(((wm * 64 + mt * 16 + mro) * KPH + kho) * 2);
#pragma unroll
    for (int ntp = 0; ntp < 4; ntp++)
        offB[ntp] = (uint32_t)(((wn * 64 + ntp * 16 + mro) * KPH + kho) * 2);

    const uint32_t ring0 = smem_u32(smem);

    // prologue: prefetch chunks 0 and 1
    stage_T(smem, 0, 0, Xbase, tid);
    cp_commit();
    stage_T(smem, 1, 1, Xbase, tid);
    cp_commit();

    int bufR = 0;
    int bufS = 2;

#pragma unroll 1
    for (int T = 0; T < TOTAL_CHUNKS; T++) {
        cp_wait<1>();        // own copies of chunk T complete
        __syncthreads();     // chunk T visible to all; slot bufS reads drained

        if (T + 2 < TOTAL_CHUNKS) stage_T(smem, bufS, T + 2, Xbase, tid);
        cp_commit();

        const uint32_t abase = ring0 + (uint32_t)bufR * STAGE_HALVES * 2u;
        const uint32_t bbase = abase + A_HALVES * 2u;

#pragma unroll
        for (int k16 = 0; k16 < 4; k16++) {
            const uint32_t kb = (uint32_t)(k16 * 32);   // 16 halves per k16 step
            uint32_t a[4][4], b[8][2];
#pragma unroll
            for (int mt = 0; mt < 4; mt++)
                ldsm4(a[mt][0], a[mt][1], a[mt][2], a[mt][3], abase + offA[mt] + kb);
#pragma unroll
            for (int ntp = 0; ntp < 4; ntp++)
                ldsm4(b[2 * ntp][0], b[2 * ntp + 1][0], b[2 * ntp][1], b[2 * ntp + 1][1],
                      bbase + offB[ntp] + kb);
#pragma unroll
            for (int mt = 0; mt < 4; mt++)
#pragma unroll
                for (int nt = 0; nt < 8; nt++)
                    mma_f16(acc[mt][nt], a[mt], b[nt]);
        }

        // ---- pass boundary: epilogue (registers + L2 table; no barrier) ----
        if ((T & (NCHUNK - 1)) == NCHUNK - 1) {
            const int p = T >> 4;
#pragma unroll
            for (int mt = 0; mt < 4; mt++) {
#pragma unroll
                for (int nt = 0; nt < 8; nt++) {
                    const int gn = p * N_TILE + wn * 64 + nt * 8 + 2 * ak;
                    const float4 w = __ldg(&vt4[gn >> 1]);   // {v0, t20, v1, t21}
                    racc[mt * 2] += w.x * tanh_fast(acc[mt][nt][0] + w.y)
                                  + w.z * tanh_fast(acc[mt][nt][1] + w.w);
                    racc[mt * 2 + 1] += w.x * tanh_fast(acc[mt][nt][2] + w.y)
                                      + w.z * tanh_fast(acc[mt][nt][3] + w.w);
                    acc[mt][nt][0] = 0.f; acc[mt][nt][1] = 0.f;
                    acc[mt][nt][2] = 0.f; acc[mt][nt][3] = 0.f;
                }
            }
        }

        bufR = (bufR == 2) ? 0 : bufR + 1;
        bufS = (bufS == 2) ? 0 : bufS + 1;
    }

    // reduce over the 4 lanes of each column group
#pragma unroll
    for (int j = 0; j < 8; j++) {
        racc[j] += __shfl_xor_sync(0xFFFFFFFFu, racc[j], 1);
        racc[j] += __shfl_xor_sync(0xFFFFFFFFu, racc[j], 2);
    }
    if (ak == 0) {
#pragma unroll
        for (int j = 0; j < 8; j++) {
            const int row = wm * 64 + (j >> 1) * 16 + ar + (j & 1) * 8;
            atomicAdd(&part[row], racc[j]);
        }
    }
    __syncthreads();
    if (tid < M_TILE) out[m0 + tid] = part[tid];
}

// ---------------- launch ----------------
extern "C" void kernel_launch(void* const* d_in, const int* in_sizes, int n_in,
                              void* d_out, int out_size) {
    const float* X  = (const float*)d_in[0];   // inputs [B,S,D]
    const float* g  = (const float*)d_in[1];   // g [B,D]
    const float* WO = (const float*)d_in[2];   // WO [SIZE,D]
    const float* WG = (const float*)d_in[3];   // WG [SIZE,D]
    const float* v  = (const float*)d_in[4];   // v [1,SIZE]
    float* out = (float*)d_out;

    __half* Xh;  cudaGetSymbolAddress((void**)&Xh,  g_Xh);
    __half* WOh; cudaGetSymbolAddress((void**)&WOh, g_WOh);

    cudaFuncSetAttribute(fused_kernel, cudaFuncAttributeMaxDynamicSharedMemorySize, SMEM_BYTES);

    const int nX4 = BB * SEQ * DD / 4;
    tohalf_kernel<<<nX4 / 256, 256>>>(X, (uint2*)Xh, nX4);
    const int nW4 = SZ * DD / 4;
    tohalf_kernel<<<nW4 / 256, 256>>>(WO, (uint2*)WOh, nW4);
    term2_kernel<<<dim3(SZ / 8, BB), 256>>>(WG, g, v);

    fused_kernel<<<(BB * SEQ) / M_TILE, THREADS, SMEM_BYTES>>>(out);
}

// round 14
// speedup vs baseline: 1.6455x; 1.0569x over previous
#include <cuda_runtime.h>
#include <cuda_fp16.h>
#include <cstdint>
#include <cstddef>

#define DEV __device__ __forceinline__

// ---------------- problem constants ----------------
static constexpr int BB = 32;
static constexpr int SEQ = 2048;
static constexpr int DD = 1024;    // K
static constexpr int SZ = 1024;    // SIZE

static constexpr int M_TILE = 128;
static constexpr int N_TILE = 128;            // 2 CTAs/SM
static constexpr int PASSES = SZ / N_TILE;    // 8
static constexpr int K_CHUNK = 64;            // halves of K per chunk
static constexpr int NCHUNK = DD / K_CHUNK;   // 16
static constexpr int TOTAL_CHUNKS = PASSES * NCHUNK;   // 128
static constexpr int THREADS = 256;           // 8 warps: 2m x 4n, warp tile 64x32
static constexpr int KPH = 72;                // halves per smem row (144 B; conflict-free)

// smem: 3-stage ring of (A|B) halves + partial buffer
static constexpr int A_HALVES = M_TILE * KPH;             // 9216
static constexpr int B_HALVES = N_TILE * KPH;             // 9216
static constexpr int STAGE_HALVES = A_HALVES + B_HALVES;  // 18432
static constexpr int NSTAGE = 3;
static constexpr int RING_BYTES = NSTAGE * STAGE_HALVES * 2;   // 110592
static constexpr int SMEM_BYTES = RING_BYTES + M_TILE * 4;     // 111104 -> 2 CTAs/SM

// scratch: fp16 copies + packed (v, term2) table
__device__ __half g_Xh[(size_t)BB * SEQ * DD];   // 128 MB
__device__ __half g_WOh[(size_t)SZ * DD];        // 2 MB
__device__ float2 g_vt2[BB * SZ];                // {v[n], term2[b][n]}

// ---------------- helpers ----------------
DEV uint32_t smem_u32(const void* p) {
    uint32_t a;
    asm("{ .reg .u64 t; cvta.to.shared.u64 t, %1; cvt.u32.u64 %0, t; }" : "=r"(a) : "l"(p));
    return a;
}
DEV void cp16(uint32_t s, const void* g) {
    asm volatile("cp.async.cg.shared.global [%0], [%1], 16;" :: "r"(s), "l"(g));
}
DEV void cp_commit() { asm volatile("cp.async.commit_group;" ::: "memory"); }
template <int N> DEV void cp_wait() { asm volatile("cp.async.wait_group %0;" :: "n"(N) : "memory"); }

DEV float tanh_fast(float x) {
    float y;
    asm("tanh.approx.f32 %0, %1;" : "=f"(y) : "f"(x));
    return y;
}

DEV void mma_f16(float* d, const uint32_t* a, const uint32_t* b) {
    asm volatile(
        "mma.sync.aligned.m16n8k16.row.col.f32.f16.f16.f32 "
        "{%0,%1,%2,%3}, {%4,%5,%6,%7}, {%8,%9}, {%0,%1,%2,%3};"
        : "+f"(d[0]), "+f"(d[1]), "+f"(d[2]), "+f"(d[3])
        : "r"(a[0]), "r"(a[1]), "r"(a[2]), "r"(a[3]), "r"(b[0]), "r"(b[1]));
}

// Stage chunk T (pass = T/16, kc = T%16) into ring slot `slot`. 256 threads.
DEV void stage_T(char* smem, int slot, int T, const __half* Xbase, int tid) {
    const int kc = T & (NCHUNK - 1);
    const int p = T >> 4;
    const __half* asrc = Xbase + kc * K_CHUNK;
    const __half* bsrc = g_WOh + (size_t)p * N_TILE * DD + kc * K_CHUNK;
    const uint32_t sa = smem_u32(smem) + (uint32_t)slot * STAGE_HALVES * 2u;
    const uint32_t sbB = sa + A_HALVES * 2u;
#pragma unroll
    for (int it = 0; it < 4; it++) {   // A: [128 x 64h] = 1024 cp16
        const int gidx = tid + it * THREADS;
        const int r = gidx >> 3, c = gidx & 7;
        cp16(sa + (uint32_t)(r * KPH * 2 + c * 16), asrc + (size_t)r * DD + c * 8);
    }
#pragma unroll
    for (int it = 0; it < 4; it++) {   // B: [128 x 64h] = 1024 cp16
        const int gidx = tid + it * THREADS;
        const int r = gidx >> 3, c = gidx & 7;
        cp16(sbB + (uint32_t)(r * KPH * 2 + c * 16), bsrc + (size_t)r * DD + c * 8);
    }
}

// ---------------- prepass: fp32 -> fp16 (rn) ----------------
__global__ void tohalf_kernel(const float* __restrict__ src, uint2* __restrict__ dst, int n4) {
    int i = blockIdx.x * blockDim.x + threadIdx.x;
    if (i >= n4) return;
    float4 u = ((const float4*)src)[i];
    __half2 h0 = __floats2half2_rn(u.x, u.y);
    __half2 h1 = __floats2half2_rn(u.z, u.w);
    uint2 o;
    o.x = *(uint32_t*)&h0;
    o.y = *(uint32_t*)&h1;
    dst[i] = o;
}

// ---------------- term2 = WG @ g, packed with v ----------------
__global__ void term2_kernel(const float* __restrict__ WG, const float* __restrict__ g,
                             const float* __restrict__ v) {
    __shared__ float4 gs[256];
    const int b = blockIdx.y;
    gs[threadIdx.x] = ((const float4*)(g + (size_t)b * DD))[threadIdx.x];
    __syncthreads();
    const int w = threadIdx.x >> 5, l = threadIdx.x & 31;
    const int n = blockIdx.x * 8 + w;
    const float4* wg4 = (const float4*)(WG + (size_t)n * DD);
    float s = 0.f;
#pragma unroll
    for (int i = 0; i < 8; i++) {
        float4 a = wg4[l + 32 * i];
        float4 gg = gs[l + 32 * i];
        s += a.x * gg.x + a.y * gg.y + a.z * gg.z + a.w * gg.w;
    }
#pragma unroll
    for (int o = 16; o; o >>= 1) s += __shfl_xor_sync(0xFFFFFFFFu, s, o);
    if (l == 0) g_vt2[b * SZ + n] = make_float2(v[n], s);
}

// ---------------- fused GEMM(fp16 mma.sync) + tanh + v-dot ----------------
__global__ __launch_bounds__(THREADS, 2)
void fused_kernel(float* __restrict__ out) {
    extern __shared__ char smem[];
    const int tid = threadIdx.x;
    const int lane = tid & 31, wid = tid >> 5;
    const int wm = wid >> 2, wn = wid & 3;      // 2 x 4 warp grid; warp tile 64x32
    const int m0 = blockIdx.x * M_TILE;
    const int bidx = m0 >> 11;

    float* part = (float*)(smem + RING_BYTES);
    for (int i = tid; i < M_TILE; i += THREADS) part[i] = 0.f;

    const __half* Xbase = g_Xh + (size_t)m0 * DD;
    const float4* vt4 = (const float4*)(g_vt2 + (size_t)bidx * SZ);

    float racc[8];
#pragma unroll
    for (int j = 0; j < 8; j++) racc[j] = 0.f;

    float acc[4][4][4];
#pragma unroll
    for (int mt = 0; mt < 4; mt++)
#pragma unroll
        for (int nt = 0; nt < 4; nt++)
#pragma unroll
            for (int q = 0; q < 4; q++) acc[mt][nt][q] = 0.f;

    const int ar = lane >> 2;   // fragment row
    const int ak = lane & 3;    // fragment k-pair

    // prologue: prefetch chunks 0 and 1
    stage_T(smem, 0, 0, Xbase, tid);
    cp_commit();
    stage_T(smem, 1, 1, Xbase, tid);
    cp_commit();

    int bufR = 0;   // slot holding chunk T
    int bufS = 2;   // slot to stage chunk T+2 into

#pragma unroll 1
    for (int T = 0; T < TOTAL_CHUNKS; T++) {
        cp_wait<1>();        // own copies of chunk T complete
        __syncthreads();     // chunk T visible to all; slot bufS reads drained

        if (T + 2 < TOTAL_CHUNKS) stage_T(smem, bufS, T + 2, Xbase, tid);
        cp_commit();         // keep group counts aligned

        const uint32_t* As = (const uint32_t*)(smem + (size_t)bufR * STAGE_HALVES * 2);
        const uint32_t* Bs = As + A_HALVES / 2;

#pragma unroll
        for (int k16 = 0; k16 < 4; k16++) {
            const int ko = k16 * 8;
            uint32_t a[4][4], b[4][2];
#pragma unroll
            for (int mt = 0; mt < 4; mt++) {
                const int r0 = (wm * 64 + mt * 16 + ar) * (KPH / 2) + ko + ak;
                a[mt][0] = As[r0];
                a[mt][1] = As[r0 + 8 * (KPH / 2)];
                a[mt][2] = As[r0 + 4];
                a[mt][3] = As[r0 + 8 * (KPH / 2) + 4];
            }
#pragma unroll
            for (int nt = 0; nt < 4; nt++) {
                const int nb = (wn * 32 + nt * 8 + ar) * (KPH / 2) + ko + ak;
                b[nt][0] = Bs[nb];
                b[nt][1] = Bs[nb + 4];
            }
#pragma unroll
            for (int mt = 0; mt < 4; mt++)
#pragma unroll
                for (int nt = 0; nt < 4; nt++)
                    mma_f16(acc[mt][nt], a[mt], b[nt]);
        }

        // ---- pass boundary: epilogue (registers + L2 table; no barrier) ----
        if ((T & (NCHUNK - 1)) == NCHUNK - 1) {
            const int p = T >> 4;
#pragma unroll
            for (int mt = 0; mt < 4; mt++) {
#pragma unroll
                for (int nt = 0; nt < 4; nt++) {
                    const int gn = p * N_TILE + wn * 32 + nt * 8 + 2 * ak;
                    const float4 w = __ldg(&vt4[gn >> 1]);   // {v0, t20, v1, t21}
                    racc[mt * 2] += w.x * tanh_fast(acc[mt][nt][0] + w.y)
                                  + w.z * tanh_fast(acc[mt][nt][1] + w.w);
                    racc[mt * 2 + 1] += w.x * tanh_fast(acc[mt][nt][2] + w.y)
                                      + w.z * tanh_fast(acc[mt][nt][3] + w.w);
                    acc[mt][nt][0] = 0.f; acc[mt][nt][1] = 0.f;
                    acc[mt][nt][2] = 0.f; acc[mt][nt][3] = 0.f;
                }
            }
        }

        bufR = (bufR == 2) ? 0 : bufR + 1;
        bufS = (bufS == 2) ? 0 : bufS + 1;
    }

    // reduce over the 4 lanes of each column group
#pragma unroll
    for (int j = 0; j < 8; j++) {
        racc[j] += __shfl_xor_sync(0xFFFFFFFFu, racc[j], 1);
        racc[j] += __shfl_xor_sync(0xFFFFFFFFu, racc[j], 2);
    }
    if (ak == 0) {
#pragma unroll
        for (int j = 0; j < 8; j++) {
            const int row = wm * 64 + (j >> 1) * 16 + ar + (j & 1) * 8;
            atomicAdd(&part[row], racc[j]);
        }
    }
    __syncthreads();
    if (tid < M_TILE) out[m0 + tid] = part[tid];
}

// ---------------- launch ----------------
extern "C" void kernel_launch(void* const* d_in, const int* in_sizes, int n_in,
                              void* d_out, int out_size) {
    const float* X  = (const float*)d_in[0];   // inputs [B,S,D]
    const float* g  = (const float*)d_in[1];   // g [B,D]
    const float* WO = (const float*)d_in[2];   // WO [SIZE,D]
    const float* WG = (const float*)d_in[3];   // WG [SIZE,D]
    const float* v  = (const float*)d_in[4];   // v [1,SIZE]
    float* out = (float*)d_out;

    __half* Xh;  cudaGetSymbolAddress((void**)&Xh,  g_Xh);
    __half* WOh; cudaGetSymbolAddress((void**)&WOh, g_WOh);

    cudaFuncSetAttribute(fused_kernel, cudaFuncAttributeMaxDynamicSharedMemorySize, SMEM_BYTES);

    const int nX4 = BB * SEQ * DD / 4;
    tohalf_kernel<<<nX4 / 256, 256>>>(X, (uint2*)Xh, nX4);
    const int nW4 = SZ * DD / 4;
    tohalf_kernel<<<nW4 / 256, 256>>>(WO, (uint2*)WOh, nW4);
    term2_kernel<<<dim3(SZ / 8, BB), 256>>>(WG, g, v);

    fused_kernel<<<(BB * SEQ) / M_TILE, THREADS, SMEM_BYTES>>>(out);
}

// round 15
// speedup vs baseline: 1.6982x; 1.0320x over previous
#include <cuda_runtime.h>
#include <cuda_fp16.h>
#include <cstdint>
#include <cstddef>

#define DEV __device__ __forceinline__

// ---------------- problem constants ----------------
static constexpr int BB = 32;
static constexpr int SEQ = 2048;
static constexpr int DD = 1024;    // K
static constexpr int SZ = 1024;    // SIZE

static constexpr int M_TILE = 128;
static constexpr int N_TILE = 128;            // 2 CTAs/SM
static constexpr int PASSES = SZ / N_TILE;    // 8
static constexpr int K_CHUNK = 64;            // halves of K per chunk
static constexpr int NCHUNK = DD / K_CHUNK;   // 16
static constexpr int TOTAL_CHUNKS = PASSES * NCHUNK;   // 128
static constexpr int THREADS = 128;           // 4 warps: 2m x 2n, warp tile 64x64
static constexpr int KPH = 72;                // halves per smem row (144 B; conflict-free)

// smem: 3-stage ring of (A|B) halves + partial buffer
static constexpr int A_HALVES = M_TILE * KPH;             // 9216
static constexpr int B_HALVES = N_TILE * KPH;             // 9216
static constexpr int STAGE_HALVES = A_HALVES + B_HALVES;  // 18432
static constexpr int NSTAGE = 3;
static constexpr int RING_BYTES = NSTAGE * STAGE_HALVES * 2;   // 110592
static constexpr int SMEM_BYTES = RING_BYTES + M_TILE * 4;     // 111104 -> 2 CTAs/SM

// unified prep kernel grid partition
static constexpr int NX4 = BB * SEQ * DD / 4;          // 16777216 uint4 elems
static constexpr int XBLK = NX4 / (256 * 8);           // 8192 blocks, 8 uint4/thread
static constexpr int NW4 = SZ * DD / 4;                // 262144
static constexpr int WBLK = NW4 / (256 * 4);           // 256 blocks, 4 uint4/thread
static constexpr int TBLK = (SZ / 8) * BB;             // 4096 term2 blocks
static constexpr int PREP_GRID = XBLK + WBLK + TBLK;   // 12544

// scratch: fp16 copies + packed (v, term2) table
__device__ __half g_Xh[(size_t)BB * SEQ * DD];   // 128 MB
__device__ __half g_WOh[(size_t)SZ * DD];        // 2 MB
__device__ float2 g_vt2[BB * SZ];                // {v[n], term2[b][n]}

// ---------------- helpers ----------------
DEV uint32_t smem_u32(const void* p) {
    uint32_t a;
    asm("{ .reg .u64 t; cvta.to.shared.u64 t, %1; cvt.u32.u64 %0, t; }" : "=r"(a) : "l"(p));
    return a;
}
DEV void cp16(uint32_t s, const void* g) {
    asm volatile("cp.async.cg.shared.global [%0], [%1], 16;" :: "r"(s), "l"(g));
}
DEV void cp_commit() { asm volatile("cp.async.commit_group;" ::: "memory"); }
template <int N> DEV void cp_wait() { asm volatile("cp.async.wait_group %0;" :: "n"(N) : "memory"); }

DEV float tanh_fast(float x) {
    float y;
    asm("tanh.approx.f32 %0, %1;" : "=f"(y) : "f"(x));
    return y;
}

DEV void mma_f16(float* d, const uint32_t* a, const uint32_t* b) {
    asm volatile(
        "mma.sync.aligned.m16n8k16.row.col.f32.f16.f16.f32 "
        "{%0,%1,%2,%3}, {%4,%5,%6,%7}, {%8,%9}, {%0,%1,%2,%3};"
        : "+f"(d[0]), "+f"(d[1]), "+f"(d[2]), "+f"(d[3])
        : "r"(a[0]), "r"(a[1]), "r"(a[2]), "r"(a[3]), "r"(b[0]), "r"(b[1]));
}

DEV uint2 cvt4(float4 u) {
    __half2 h0 = __floats2half2_rn(u.x, u.y);
    __half2 h1 = __floats2half2_rn(u.z, u.w);
    uint2 o;
    o.x = *(uint32_t*)&h0;
    o.y = *(uint32_t*)&h1;
    return o;
}

// Stage chunk T (pass = T/16, kc = T%16) into ring slot `slot`. 128 threads.
DEV void stage_T(char* smem, int slot, int T, const __half* Xbase, int tid) {
    const int kc = T & (NCHUNK - 1);
    const int p = T >> 4;
    const __half* asrc = Xbase + kc * K_CHUNK;
    const __half* bsrc = g_WOh + (size_t)p * N_TILE * DD + kc * K_CHUNK;
    const uint32_t sa = smem_u32(smem) + (uint32_t)slot * STAGE_HALVES * 2u;
    const uint32_t sbB = sa + A_HALVES * 2u;
#pragma unroll
    for (int it = 0; it < 8; it++) {   // A: [128 x 64h] = 1024 cp16
        const int gidx = tid + it * THREADS;
        const int r = gidx >> 3, c = gidx & 7;
        cp16(sa + (uint32_t)(r * KPH * 2 + c * 16), asrc + (size_t)r * DD + c * 8);
    }
#pragma unroll
    for (int it = 0; it < 8; it++) {   // B: [128 x 64h] = 1024 cp16
        const int gidx = tid + it * THREADS;
        const int r = gidx >> 3, c = gidx & 7;
        cp16(sbB + (uint32_t)(r * KPH * 2 + c * 16), bsrc + (size_t)r * DD + c * 8);
    }
}

// ---------------- unified prep: X->fp16, WO->fp16, term2+v pack ----------------
__global__ void prep_kernel(const float4* __restrict__ X, const float4* __restrict__ WO,
                            const float* __restrict__ WG, const float* __restrict__ g,
                            const float* __restrict__ v) {
    const int bx = blockIdx.x;
    const int tid = threadIdx.x;

    if (bx < XBLK) {
        // ---- X fp32 -> fp16 : 8 uint4 per thread, streaming reads ----
        uint2* dst = (uint2*)g_Xh;
        const int base = bx * 2048 + tid;
#pragma unroll
        for (int it = 0; it < 8; it++) {
            const int i = base + it * 256;
            dst[i] = cvt4(__ldcs(&X[i]));
        }
        return;
    }
    if (bx < XBLK + WBLK) {
        // ---- WO fp32 -> fp16 : 4 uint4 per thread ----
        uint2* dst = (uint2*)g_WOh;
        const int base = (bx - XBLK) * 1024 + tid;
#pragma unroll
        for (int it = 0; it < 4; it++) {
            const int i = base + it * 256;
            dst[i] = cvt4(__ldcs(&WO[i]));
        }
        return;
    }

    // ---- term2 = WG @ g, packed with v ----
    __shared__ float4 gs[256];
    const int tb = bx - XBLK - WBLK;        // 0..4095
    const int nblk = tb & ((SZ / 8) - 1);   // 0..127
    const int b = tb >> 7;                  // 0..31
    gs[tid] = ((const float4*)(g + (size_t)b * DD))[tid];
    __syncthreads();
    const int w = tid >> 5, l = tid & 31;
    const int n = nblk * 8 + w;
    const float4* wg4 = (const float4*)(WG + (size_t)n * DD);
    float s = 0.f;
#pragma unroll
    for (int i = 0; i < 8; i++) {
        float4 a = wg4[l + 32 * i];
        float4 gg = gs[l + 32 * i];
        s += a.x * gg.x + a.y * gg.y + a.z * gg.z + a.w * gg.w;
    }
#pragma unroll
    for (int o = 16; o; o >>= 1) s += __shfl_xor_sync(0xFFFFFFFFu, s, o);
    if (l == 0) g_vt2[b * SZ + n] = make_float2(v[n], s);
}

// ---------------- fused GEMM(fp16 mma.sync) + tanh + v-dot  (R10, frozen) ----------------
__global__ __launch_bounds__(THREADS, 2)
void fused_kernel(float* __restrict__ out) {
    extern __shared__ char smem[];
    const int tid = threadIdx.x;
    const int lane = tid & 31, wid = tid >> 5;
    const int wm = wid >> 1, wn = wid & 1;      // 2 x 2 warp grid; warp tile 64x64
    const int m0 = blockIdx.x * M_TILE;
    const int bidx = m0 >> 11;

    float* part = (float*)(smem + RING_BYTES);
    for (int i = tid; i < M_TILE; i += THREADS) part[i] = 0.f;

    const __half* Xbase = g_Xh + (size_t)m0 * DD;
    const float4* vt4 = (const float4*)(g_vt2 + (size_t)bidx * SZ);

    float racc[8];
#pragma unroll
    for (int j = 0; j < 8; j++) racc[j] = 0.f;

    float acc[4][8][4];
#pragma unroll
    for (int mt = 0; mt < 4; mt++)
#pragma unroll
        for (int nt = 0; nt < 8; nt++)
#pragma unroll
            for (int q = 0; q < 4; q++) acc[mt][nt][q] = 0.f;

    const int ar = lane >> 2;   // fragment row
    const int ak = lane & 3;    // fragment k-pair

    // prologue: prefetch chunks 0 and 1
    stage_T(smem, 0, 0, Xbase, tid);
    cp_commit();
    stage_T(smem, 1, 1, Xbase, tid);
    cp_commit();

    int bufR = 0;   // slot holding chunk T
    int bufS = 2;   // slot to stage chunk T+2 into

#pragma unroll 1
    for (int T = 0; T < TOTAL_CHUNKS; T++) {
        cp_wait<1>();        // own copies of chunk T complete
        __syncthreads();     // chunk T visible to all; slot bufS reads drained

        if (T + 2 < TOTAL_CHUNKS) stage_T(smem, bufS, T + 2, Xbase, tid);
        cp_commit();         // keep group counts aligned

        const uint32_t* As = (const uint32_t*)(smem + (size_t)bufR * STAGE_HALVES * 2);
        const uint32_t* Bs = As + A_HALVES / 2;

#pragma unroll
        for (int k16 = 0; k16 < 4; k16++) {
            const int ko = k16 * 8;
            uint32_t a[4][4], b[8][2];
#pragma unroll
            for (int mt = 0; mt < 4; mt++) {
                const int r0 = (wm * 64 + mt * 16 + ar) * (KPH / 2) + ko + ak;
                a[mt][0] = As[r0];
                a[mt][1] = As[r0 + 8 * (KPH / 2)];
                a[mt][2] = As[r0 + 4];
                a[mt][3] = As[r0 + 8 * (KPH / 2) + 4];
            }
#pragma unroll
            for (int nt = 0; nt < 8; nt++) {
                const int nb = (wn * 64 + nt * 8 + ar) * (KPH / 2) + ko + ak;
                b[nt][0] = Bs[nb];
                b[nt][1] = Bs[nb + 4];
            }
#pragma unroll
            for (int mt = 0; mt < 4; mt++)
#pragma unroll
                for (int nt = 0; nt < 8; nt++)
                    mma_f16(acc[mt][nt], a[mt], b[nt]);
        }

        // ---- pass boundary: epilogue (registers + L2 table; no barrier) ----
        if ((T & (NCHUNK - 1)) == NCHUNK - 1) {
            const int p = T >> 4;
#pragma unroll
            for (int mt = 0; mt < 4; mt++) {
#pragma unroll
                for (int nt = 0; nt < 8; nt++) {
                    const int gn = p * N_TILE + wn * 64 + nt * 8 + 2 * ak;
                    const float4 w = __ldg(&vt4[gn >> 1]);   // {v0, t20, v1, t21}
                    racc[mt * 2] += w.x * tanh_fast(acc[mt][nt][0] + w.y)
                                  + w.z * tanh_fast(acc[mt][nt][1] + w.w);
                    racc[mt * 2 + 1] += w.x * tanh_fast(acc[mt][nt][2] + w.y)
                                      + w.z * tanh_fast(acc[mt][nt][3] + w.w);
                    acc[mt][nt][0] = 0.f; acc[mt][nt][1] = 0.f;
                    acc[mt][nt][2] = 0.f; acc[mt][nt][3] = 0.f;
                }
            }
        }

        bufR = (bufR == 2) ? 0 : bufR + 1;
        bufS = (bufS == 2) ? 0 : bufS + 1;
    }

    // reduce over the 4 lanes of each column group
#pragma unroll
    for (int j = 0; j < 8; j++) {
        racc[j] += __shfl_xor_sync(0xFFFFFFFFu, racc[j], 1);
        racc[j] += __shfl_xor_sync(0xFFFFFFFFu, racc[j], 2);
    }
    if (ak == 0) {
#pragma unroll
        for (int j = 0; j < 8; j++) {
            const int row = wm * 64 + (j >> 1) * 16 + ar + (j & 1) * 8;
            atomicAdd(&part[row], racc[j]);
        }
    }
    __syncthreads();
    if (tid < M_TILE) out[m0 + tid] = part[tid];
}

// ---------------- launch ----------------
extern "C" void kernel_launch(void* const* d_in, const int* in_sizes, int n_in,
                              void* d_out, int out_size) {
    const float* X  = (const float*)d_in[0];   // inputs [B,S,D]
    const float* g  = (const float*)d_in[1];   // g [B,D]
    const float* WO = (const float*)d_in[2];   // WO [SIZE,D]
    const float* WG = (const float*)d_in[3];   // WG [SIZE,D]
    const float* v  = (const float*)d_in[4];   // v [1,SIZE]
    float* out = (float*)d_out;

    cudaFuncSetAttribute(fused_kernel, cudaFuncAttributeMaxDynamicSharedMemorySize, SMEM_BYTES);

    prep_kernel<<<PREP_GRID, 256>>>((const float4*)X, (const float4*)WO, WG, g, v);
    fused_kernel<<<(BB * SEQ) / M_TILE, THREADS, SMEM_BYTES>>>(out);
}